// round 1
// baseline (speedup 1.0000x reference)
#include <cuda_runtime.h>
#include <stdint.h>

#define B_SZ 65536
#define NM 5
#define WARPS_PER_BLOCK 8
#define NBLOCKS (B_SZ / WARPS_PER_BLOCK)  // 8192

__device__ float g_partials[NBLOCKS];

__device__ __forceinline__ float sqrt_ap(float x) {
    float r;
    asm("sqrt.approx.f32 %0, %1;" : "=f"(r) : "f"(x));
    return r;
}

// Smooth-L1 (huber, delta=1): ad<1 ? 0.5 d^2 : ad-0.5  ==  t*(ad - 0.5 t), t=min(ad,1)
__device__ __forceinline__ float huber(float d) {
    float ad = fabsf(d);
    float t = fminf(ad, 1.0f);
    return t * fmaf(-0.5f, t, ad);
}

__device__ __forceinline__ uint32_t rotl32(uint32_t x, uint32_t d) {
    return __funnelshift_l(x, x, d);
}

// JAX partitionable ThreeFry-2x32: key=(0,42), counter=(0,i); randint(0,5) -> (x0^x1) % 5
__device__ __forceinline__ int threefry_mod5(uint32_t i) {
    const uint32_t k0 = 0u, k1 = 42u;
    const uint32_t k2 = k0 ^ k1 ^ 0x1BD11BDAu;
    uint32_t x0 = k0;        // hi counter = 0
    uint32_t x1 = i + k1;    // lo counter = i
#define TF4(r0, r1, r2, r3)                           \
    x0 += x1; x1 = rotl32(x1, r0); x1 ^= x0;          \
    x0 += x1; x1 = rotl32(x1, r1); x1 ^= x0;          \
    x0 += x1; x1 = rotl32(x1, r2); x1 ^= x0;          \
    x0 += x1; x1 = rotl32(x1, r3); x1 ^= x0;
    TF4(13, 15, 26, 6)   x0 += k1; x1 += k2 + 1u;
    TF4(17, 29, 16, 24)  x0 += k2; x1 += k0 + 2u;
    TF4(13, 15, 26, 6)   x0 += k0; x1 += k1 + 3u;
    TF4(17, 29, 16, 24)  x0 += k1; x1 += k2 + 4u;
    TF4(13, 15, 26, 6)   x0 += k2; x1 += k0 + 5u;
#undef TF4
    return (int)((x0 ^ x1) % 5u);
}

__global__ void __launch_bounds__(32 * WARPS_PER_BLOCK)
combo_main(const float* __restrict__ path_pred,
           const float* __restrict__ path_gt,
           const float* __restrict__ cr_pred,
           const float* __restrict__ cr_gt) {
    __shared__ float warp_sums[WARPS_PER_BLOCK];
    const unsigned FULL = 0xffffffffu;
    int lane = threadIdx.x & 31;
    int w = threadIdx.x >> 5;
    int s = blockIdx.x * WARPS_PER_BLOCK + w;

    const float* tp = path_pred + (size_t)s * 505;           // 5*50*2 traj + 5 probs
    const float2* gt2 = (const float2*)(path_gt + (size_t)s * 100);  // 400B-aligned rows

    // lane handles t = lane (always) and t = 32+lane (lane < 18)
    float2 g0 = gt2[lane];
    bool has2 = (lane < 18);
    float2 g1 = make_float2(0.f, 0.f);
    if (has2) g1 = gt2[32 + lane];

    // scalar loads: 505-float rows are not float2-aligned for odd s
    const float* b0 = tp + 2 * lane;
    const float* b1 = tp + 2 * (32 + lane);

    float dist[NM], regs[NM], tlx[NM], tly[NM];
#pragma unroll
    for (int m = 0; m < NM; m++) {
        float x0 = b0[m * 100], y0 = b0[m * 100 + 1];
        float dx = x0 - g0.x, dy = y0 - g0.y;
        float dsum = sqrt_ap(fmaf(dx, dx, dy * dy));
        float rsum = huber(dx) + huber(dy);
        float x1v = 0.f, y1v = 0.f;
        if (has2) {
            x1v = b1[m * 100]; y1v = b1[m * 100 + 1];
            float ex = x1v - g1.x, ey = y1v - g1.y;
            dsum += sqrt_ap(fmaf(ex, ex, ey * ey));
            rsum += huber(ex) + huber(ey);
        }
#pragma unroll
        for (int o = 16; o; o >>= 1) {
            dsum += __shfl_xor_sync(FULL, dsum, o);
            rsum += __shfl_xor_sync(FULL, rsum, o);
        }
        dist[m] = dsum;                                  // sum over t (argmin-invariant scale)
        regs[m] = rsum;                                  // sum of huber over 50x2
        tlx[m] = __shfl_sync(FULL, x1v, 17);             // traj[m][49] lives on lane 17
        tly[m] = __shfl_sync(FULL, y1v, 17);
    }
    float refx = __shfl_sync(FULL, g1.x, 17);            // path_gt[49]
    float refy = __shfl_sync(FULL, g1.y, 17);
    float rn = sqrt_ap(fmaf(refx, refx, refy * refy));
    bool ref_nan = isnan(refx) || isnan(refy);

    // eligible  <=>  angle <= 5deg  <=>  dot >= cos(5deg)*nprod  (nprod>0, no NaN)
    const float COS5 = 0.99619469809174553f;
    const float INF = __int_as_float(0x7f800000);
    float bestKey = INF;
    int best = 0;
    bool any = false;
#pragma unroll
    for (int m = 0; m < NM; m++) {
        float tn = sqrt_ap(fmaf(tlx[m], tlx[m], tly[m] * tly[m]));
        float nprod = rn * tn;
        float dot = fmaf(refx, tlx[m], refy * tly[m]);
        bool nanm = ref_nan || isnan(tlx[m]) || isnan(tly[m]);
        bool elig;
        if (nanm)               elig = false;            // angle := 180 - eps
        else if (nprod == 0.f)  elig = true;             // angle := 0
        else                    elig = (dot >= COS5 * nprod);
        any |= elig;
        float key = elig ? dist[m] : INF;
        if (key < bestKey) { bestKey = key; best = m; }  // strict < => first-min like argmin
    }
    if (!any) best = threefry_mod5((uint32_t)s);         // warp-uniform branch

    // cross-entropy via log_softmax over the 5 mode logits
    float pr = (lane < NM) ? tp[500 + lane] : -INF;
    float mx = pr;
#pragma unroll
    for (int o = 16; o; o >>= 1) mx = fmaxf(mx, __shfl_xor_sync(FULL, mx, o));
    float e = (lane < NM) ? __expf(pr - mx) : 0.f;
#pragma unroll
    for (int o = 16; o; o >>= 1) e += __shfl_xor_sync(FULL, e, o);
    float lse = mx + __logf(e);
    float pbest = __shfl_sync(FULL, pr, best);
    float ce = lse - pbest;

    float rb = regs[0];
#pragma unroll
    for (int m = 1; m < NM; m++) rb = (best == m) ? regs[m] : rb;
    rb = rb / 100.0f;                                    // mean over (50, 2)

    if (lane == 0) {
        float p = cr_pred[s], y = cr_gt[s];
        float lp  = fmaxf(__logf(p), -100.0f);
        float l1p = fmaxf(log1pf(-p), -100.0f);
        float bce = -(y * lp + (1.0f - y) * l1p);
        warp_sums[w] = ce + rb + bce;
    }
    __syncthreads();
    if (threadIdx.x == 0) {
        float t = 0.f;
#pragma unroll
        for (int i = 0; i < WARPS_PER_BLOCK; i++) t += warp_sums[i];
        g_partials[blockIdx.x] = t;
    }
}

__global__ void __launch_bounds__(256) combo_reduce(float* __restrict__ out) {
    __shared__ float sm[256];
    float t = 0.f;
    for (int i = threadIdx.x; i < NBLOCKS; i += 256) t += g_partials[i];
    sm[threadIdx.x] = t;
    __syncthreads();
    for (int st = 128; st; st >>= 1) {
        if (threadIdx.x < st) sm[threadIdx.x] += sm[threadIdx.x + st];
        __syncthreads();
    }
    if (threadIdx.x == 0) out[0] = sm[0] * (1.0f / (float)B_SZ);
}

extern "C" void kernel_launch(void* const* d_in, const int* in_sizes, int n_in,
                              void* d_out, int out_size) {
    const float* path_pred = (const float*)d_in[0];
    const float* path_gt   = (const float*)d_in[1];
    const float* cr_pred   = (const float*)d_in[2];
    const float* cr_gt     = (const float*)d_in[3];
    // d_in[4] = log_vars (unused by the reference's returned value)
    combo_main<<<NBLOCKS, 32 * WARPS_PER_BLOCK>>>(path_pred, path_gt, cr_pred, cr_gt);
    combo_reduce<<<1, 256>>>((float*)d_out);
}